// round 9
// baseline (speedup 1.0000x reference)
#include <cuda_runtime.h>
#include <cstdint>

// CRPS loss — phase-split load/compute interleave, packed f32x2.
//   term1 = mean_i |s_i - y| ; term2 = sum_{i<j}|s_i - s_j| / 256
//   out   = mean_pixels (term1 - term2)
//
// samples: [16, 4, 1, 256, 256] f32 -> 16 planes of 262144 floats
// target:  [4, 1, 256, 256]     f32 -> 262144 floats
//
// 1024 CTAs x 128 threads, one float2 pixel-pair per thread.
// Loads issued in two groups of 8+1 / 8; phase-A compute consumes ONLY the
// first group (in load order) while the second group is in flight.

#define NS      16
#define NPIX    (4 * 1 * 256 * 256)     // 262144
#define THREADS 128
#define BLOCKS  (NPIX / 2 / THREADS)    // 1024

__device__ float        g_partial[BLOCKS];
__device__ unsigned int g_done = 0;

// ---- packed f32x2 helpers (sm_103a) ----
__device__ __forceinline__ uint64_t fadd2(uint64_t a, uint64_t b) {
    uint64_t r; asm("add.rn.f32x2 %0, %1, %2;" : "=l"(r) : "l"(a), "l"(b)); return r;
}
__device__ __forceinline__ uint64_t ffma2(uint64_t a, uint64_t b, uint64_t c) {
    uint64_t r; asm("fma.rn.f32x2 %0, %1, %2, %3;" : "=l"(r) : "l"(a), "l"(b), "l"(c)); return r;
}
__device__ __forceinline__ uint64_t fabs2(uint64_t a) {
    return a & 0x7FFFFFFF7FFFFFFFULL;       // sign-clear both lanes (alu pipe)
}
__device__ __forceinline__ float2 unpack2(uint64_t v) {
    float lo, hi; asm("mov.b64 {%0, %1}, %2;" : "=f"(lo), "=f"(hi) : "l"(v));
    return make_float2(lo, hi);
}
#define NEG_ONE2 0xBF800000BF800000ULL      // {-1.0f, -1.0f}

// |a - b| packed, accumulated: acc += |a - b|
#define PAIR(acc, a, b) (acc) = fadd2((acc), fabs2(ffma2((b), NEG_ONE2, (a))))

__global__ __launch_bounds__(THREADS) void crps_fused_kernel(
    const float* __restrict__ samples,
    const float* __restrict__ target,
    float* __restrict__ out)
{
    const int tid = threadIdx.x;
    const int v   = blockIdx.x * THREADS + tid;   // float2 group (2 pixels)

    uint64_t s[NS];

    // ---- load group 1: s[0..7] + target (9 x LDG.64) ----
#pragma unroll
    for (int i = 0; i < 8; i++)
        s[i] = reinterpret_cast<const uint64_t*>(samples + (size_t)i * NPIX)[v];
    const uint64_t y = reinterpret_cast<const uint64_t*>(target)[v];

    // ---- load group 2: s[8..15] (8 x LDG.64, in flight during phase A) ----
#pragma unroll
    for (int i = 8; i < NS; i++)
        s[i] = reinterpret_cast<const uint64_t*>(samples + (size_t)i * NPIX)[v];

    uint64_t t1a = 0, t1b = 0;
    uint64_t t2[4] = {0, 0, 0, 0};

    // ---- phase A: consumes ONLY s[0..7] and y, in load order ----
#pragma unroll
    for (int i = 0; i < 8; i += 2) {
        PAIR(t1a, s[i],     y);
        PAIR(t1b, s[i + 1], y);
    }
    {
        int c = 0;
#pragma unroll
        for (int i = 0; i < 8; i++) {
#pragma unroll
            for (int j = i + 1; j < 8; j++) {          // 28 pairs
                PAIR(t2[c & 3], s[i], s[j]);
                c++;
            }
        }
    }

    // ---- phase B: everything touching s[8..15] ----
#pragma unroll
    for (int i = 8; i < NS; i += 2) {
        PAIR(t1a, s[i],     y);
        PAIR(t1b, s[i + 1], y);
    }
    {
        int c = 0;
#pragma unroll
        for (int i = 8; i < NS; i++) {
#pragma unroll
            for (int j = 0; j < i; j++) {              // 8..15 vs all earlier: 92 pairs
                PAIR(t2[c & 3], s[i], s[j]);
                c++;
            }
        }
    }

    const float2 p1 = unpack2(fadd2(t1a, t1b));
    const float2 p2 = unpack2(fadd2(fadd2(t2[0], t2[1]), fadd2(t2[2], t2[3])));
    float val = (p1.x + p1.y) * (1.0f / NS)
              - (p2.x + p2.y) * (1.0f / (NS * NS));

    // ---- block reduction (4 warps) ----
    __shared__ float warp_sum[THREADS / 32];
    float w = val;
#pragma unroll
    for (int off = 16; off > 0; off >>= 1)
        w += __shfl_down_sync(0xFFFFFFFFu, w, off);
    if ((tid & 31) == 0) warp_sum[tid >> 5] = w;
    __syncthreads();

    __shared__ bool is_last;
    if (tid == 0) {
        float b = (warp_sum[0] + warp_sum[1]) + (warp_sum[2] + warp_sum[3]);
        g_partial[blockIdx.x] = b;
        __threadfence();
        unsigned int ticket = atomicAdd(&g_done, 1u);
        is_last = (ticket == BLOCKS - 1);
    }
    __syncthreads();

    // ---- last block folds the 1024 partials ----
    if (is_last) {
        float acc = 0.0f;
#pragma unroll
        for (int k = 0; k < BLOCKS / THREADS; k++)
            acc += g_partial[tid + k * THREADS];
#pragma unroll
        for (int off = 16; off > 0; off >>= 1)
            acc += __shfl_down_sync(0xFFFFFFFFu, acc, off);
        if ((tid & 31) == 0) warp_sum[tid >> 5] = acc;
        __syncthreads();
        if (tid == 0) {
            float total = (warp_sum[0] + warp_sum[1]) + (warp_sum[2] + warp_sum[3]);
            out[0] = total * (1.0f / NPIX);
            g_done = 0;                  // reset for next graph replay
        }
    }
}

extern "C" void kernel_launch(void* const* d_in, const int* in_sizes, int n_in,
                              void* d_out, int out_size)
{
    const float* samples = (const float*)d_in[0];
    const float* target  = (const float*)d_in[1];
    crps_fused_kernel<<<BLOCKS, THREADS>>>(samples, target, (float*)d_out);
}